// round 9
// baseline (speedup 1.0000x reference)
#include <cuda_runtime.h>
#include <cuda_bf16.h>
#include <cstdint>
#include <cstddef>

#define BB 128
#define NN 400
#define FF 128
#define KNN 5
#define CAND 8
#define BN (BB * NN)   // 51200

// ---------------- device scratch ----------------
__device__ float g_sq[BN];
__device__ unsigned int g_Abits[(size_t)BN * 16];            // 400-bit adjacency rows
__device__ float g_m[(size_t)BN * FF];
__device__ float g_h[(size_t)BN * FF];
__device__ unsigned char g_xh[(size_t)512 * 32768];          // bf16-hi tiles, pre-swizzled
__device__ unsigned char g_xl[(size_t)512 * 32768];          // bf16-lo tiles

// ---------------- warp-MMA helpers (base-target PTX) ----------------
__device__ __forceinline__ uint32_t smem_u32(const void* p) {
    uint32_t a;
    asm("{ .reg .u64 t; cvta.to.shared.u64 t, %1; cvt.u32.u64 %0, t; }" : "=r"(a) : "l"(p));
    return a;
}
__device__ __forceinline__ void ldm_x4(uint32_t* r, uint32_t addr) {
    asm volatile("ldmatrix.sync.aligned.m8n8.x4.shared.b16 {%0,%1,%2,%3}, [%4];"
        : "=r"(r[0]), "=r"(r[1]), "=r"(r[2]), "=r"(r[3]) : "r"(addr));
}
__device__ __forceinline__ void mma16816(float* c, const uint32_t* a, const uint32_t* b) {
    asm volatile("mma.sync.aligned.m16n8k16.row.col.f32.bf16.bf16.f32 "
        "{%0,%1,%2,%3}, {%4,%5,%6,%7}, {%8,%9}, {%0,%1,%2,%3};"
        : "+f"(c[0]), "+f"(c[1]), "+f"(c[2]), "+f"(c[3])
        : "r"(a[0]), "r"(a[1]), "r"(a[2]), "r"(a[3]), "r"(b[0]), "r"(b[1]));
}
// bf16 tile: 128 rows x 128 cols, 256B/row, 16B-unit swizzle u' = u ^ (row&7)
__device__ __forceinline__ uint32_t toff(int row, int k) {
    return (uint32_t)(row * 256 + ((((k >> 3) ^ (row & 7)) << 4) | ((k & 7) << 1)));
}
__device__ __forceinline__ uint32_t pk_bf(__nv_bfloat16 a, __nv_bfloat16 b) {
    return (uint32_t)__bfloat16_as_ushort(a) | ((uint32_t)__bfloat16_as_ushort(b) << 16);
}

// ---------------- squared norms ----------------
__global__ void sq_kernel(const float* __restrict__ x) {
    int row = blockIdx.x * 4 + (threadIdx.x >> 5);
    int lane = threadIdx.x & 31;
    float4 v = *(const float4*)(x + (size_t)row * FF + lane * 4);
    float s = v.x * v.x + v.y * v.y + v.z * v.z + v.w * v.w;
#pragma unroll
    for (int o = 16; o; o >>= 1) s += __shfl_xor_sync(0xffffffffu, s, o);
    if (lane == 0) g_sq[row] = s;
}

// ---------------- pre-split x into bf16 hi/lo swizzled tiles ----------------
__global__ void xsplit_kernel(const float* __restrict__ x) {
    int it = blockIdx.x, b = blockIdx.y, t = threadIdx.x;
    size_t tbase = (size_t)(b * 4 + it) * 32768;
    for (int idx = t; idx < 4096; idx += 256) {
        int row = idx >> 5, c4 = (idx & 31) << 2;
        int node = it * 128 + row;
        float4 v = (node < NN) ? *(const float4*)(x + ((size_t)b * NN + node) * FF + c4)
                               : make_float4(0.f, 0.f, 0.f, 0.f);
        __nv_bfloat16 h0 = __float2bfloat16(v.x), h1 = __float2bfloat16(v.y);
        __nv_bfloat16 h2 = __float2bfloat16(v.z), h3 = __float2bfloat16(v.w);
        uint32_t off = toff(row, c4);
        *(uint2*)(g_xh + tbase + off) = make_uint2(pk_bf(h0, h1), pk_bf(h2, h3));
        *(uint2*)(g_xl + tbase + off) = make_uint2(
            pk_bf(__float2bfloat16(v.x - __bfloat162float(h0)), __float2bfloat16(v.y - __bfloat162float(h1))),
            pk_bf(__float2bfloat16(v.z - __bfloat162float(h2)), __float2bfloat16(v.w - __bfloat162float(h3))));
    }
}

// ---------------- tensor-core kNN: approx top-8 + exact rerank top-5 ----------------
// smem: Ah 32k | Al 32k | Bh 16k | Bl 16k | sc 128x68 f | sq 448 f | bv 128x8 f | bi 128x8 i | tv 8x8 f | ti 8x8 i
#define KNN2_SMEM 143616

__global__ void __launch_bounds__(256) knn2_kernel(const float* __restrict__ x) {
    extern __shared__ char dsm[];
    char* sAh = dsm;
    char* sAl = dsm + 32768;
    char* sBh = dsm + 65536;
    char* sBl = dsm + 81920;
    float* s_sc = (float*)(dsm + 98304);        // 128 x 68
    float* s_sq = (float*)(dsm + 133120);       // 448
    float* s_bv = (float*)(dsm + 134912);       // 128 x 8
    int*   s_bi = (int*)(dsm + 139008);         // 128 x 8
    float* s_tv = (float*)(dsm + 143104);       // 8 x 8
    int*   s_ti = (int*)(dsm + 143360);         // 8 x 8
    const uint32_t aA = smem_u32(dsm);
    const uint32_t aB = aA + 65536;

    const int it = blockIdx.x, b = blockIdx.y;
    const int t = threadIdx.x;
    const int wid = t >> 5, lane = t & 31;
    const int wm = wid & 3, wn = wid >> 2;
    const float INF = __int_as_float(0x7f800000);

    // ldmatrix lane bases (identical machinery to mma_gemm)
    const int mat = lane >> 3, mrow = lane & 7;
    const int arow = wm * 32 + ((mat & 1) << 3) + mrow;
    const int aku  = mat >> 1;
    const int ar7  = arow & 7;
    const int brow = wn * 32 + ((mat >> 1) << 3) + mrow;
    const int bku  = mat & 1;
    const int br7  = brow & 7;

    // load A tiles (this block's 128 i-rows), fill sq + candidate lists
    {
        const uint4* srcH = (const uint4*)(g_xh + (size_t)(b * 4 + it) * 32768);
        const uint4* srcL = (const uint4*)(g_xl + (size_t)(b * 4 + it) * 32768);
        for (int idx = t; idx < 2048; idx += 256) {
            ((uint4*)sAh)[idx] = srcH[idx];
            ((uint4*)sAl)[idx] = srcL[idx];
        }
        for (int j = t; j < 448; j += 256) s_sq[j] = (j < NN) ? g_sq[b * NN + j] : INF;
        for (int q = t; q < 128 * CAND; q += 256) { s_bv[q] = INF; s_bi[q] = 0x7fffffff; }
    }

    for (int jt = 0; jt < 7; jt++) {
        const int j0 = jt * 64;
        {
            size_t boff = (size_t)(b * 4 + (j0 >> 7)) * 32768 + (size_t)(j0 & 127) * 256;
            const uint4* srcH = (const uint4*)(g_xh + boff);
            const uint4* srcL = (const uint4*)(g_xl + boff);
            for (int idx = t; idx < 1024; idx += 256) {
                ((uint4*)sBh)[idx] = srcH[idx];
                ((uint4*)sBl)[idx] = srcL[idx];
            }
        }
        __syncthreads();

        float c[2][4][4] = {};
#pragma unroll
        for (int pass = 0; pass < 3; pass++) {
            const uint32_t baseA = aA + (pass == 2 ? 32768u : 0u);
            const uint32_t baseB = aB + (pass == 1 ? 16384u : 0u);
            const uint32_t rowA0 = baseA + (uint32_t)arow * 256;
            const uint32_t rowA1 = rowA0 + 16 * 256;
            const uint32_t rowB0 = baseB + (uint32_t)brow * 256;
#pragma unroll
            for (int ks = 0; ks < 8; ks++) {
                uint32_t a0[4], a1[4], b0[4], b1[4];
                uint32_t ua = (uint32_t)(((ks * 2 + aku) ^ ar7) << 4);
                ldm_x4(a0, rowA0 + ua);
                ldm_x4(a1, rowA1 + ua);
                uint32_t ub = (uint32_t)(((ks * 2 + bku) ^ br7) << 4);
                ldm_x4(b0, rowB0 + ub);
                ldm_x4(b1, rowB0 + 16 * 256 + ub);
                mma16816(c[0][0], a0, &b0[0]); mma16816(c[0][1], a0, &b0[2]);
                mma16816(c[0][2], a0, &b1[0]); mma16816(c[0][3], a0, &b1[2]);
                mma16816(c[1][0], a1, &b0[0]); mma16816(c[1][1], a1, &b0[2]);
                mma16816(c[1][2], a1, &b1[0]); mma16816(c[1][3], a1, &b1[2]);
            }
        }
        // dump scores: sc[row][col] = sq[j] - 2*dot
#pragma unroll
        for (int mt = 0; mt < 2; mt++)
#pragma unroll
            for (int nf = 0; nf < 4; nf++)
#pragma unroll
                for (int e = 0; e < 4; e++) {
                    int row = wm * 32 + mt * 16 + (lane >> 2) + ((e >> 1) << 3);
                    int col = wn * 32 + nf * 8 + (lane & 3) * 2 + (e & 1);
                    s_sc[row * 68 + col] = s_sq[j0 + col] - 2.f * c[mt][nf][e];
                }
        __syncthreads();

        // per-row top-8 of this tile merged into running list (warp owns 16 rows)
        for (int rr = 0; rr < 16; rr++) {
            int row = wid * 16 + rr;
            int node = it * 128 + row;
            if (node < NN) {
                float2 sp = *(float2*)&s_sc[row * 68 + lane * 2];
                float sc0 = sp.x, sc1 = sp.y;
                int jg0 = j0 + lane * 2, jg1 = jg0 + 1;
                float kv = s_bv[row * CAND + (CAND - 1)];
                int   ki = s_bi[row * CAND + (CAND - 1)];
                bool cand = (sc0 < kv) || (sc0 == kv && jg0 < ki) ||
                            (sc1 < kv) || (sc1 == kv && jg1 < ki);
                if (__ballot_sync(0xffffffffu, cand)) {
                    if (lane < CAND) { s_tv[wid * CAND + lane] = INF; s_ti[wid * CAND + lane] = 0x7fffffff; }
                    __syncwarp();
                    for (int q = 0; q < CAND; q++) {
                        float bv; int bj;
                        if (sc0 < sc1 || (sc0 == sc1 && jg0 < jg1)) { bv = sc0; bj = jg0; }
                        else { bv = sc1; bj = jg1; }
#pragma unroll
                        for (int o = 16; o; o >>= 1) {
                            float ov = __shfl_xor_sync(0xffffffffu, bv, o);
                            int   oj = __shfl_xor_sync(0xffffffffu, bj, o);
                            if (ov < bv || (ov == bv && oj < bj)) { bv = ov; bj = oj; }
                        }
                        bool beats = (bv < kv) || (bv == kv && bj < ki);
                        if (!beats) break;
                        if (lane == 0) { s_tv[wid * CAND + q] = bv; s_ti[wid * CAND + q] = bj; }
                        if (bj == jg0) sc0 = INF;
                        if (bj == jg1) sc1 = INF;
                    }
                    __syncwarp();
                    if (lane == 0) {
                        float rv[CAND]; int ri[CAND];
                        float* av = &s_bv[row * CAND]; int* ai = &s_bi[row * CAND];
                        float* tv = &s_tv[wid * CAND]; int* ti = &s_ti[wid * CAND];
                        int p = 0, q = 0;
#pragma unroll
                        for (int o = 0; o < CAND; o++) {
                            float va = av[p], vt = tv[q];
                            bool takeA = (va < vt) || (va == vt && ai[p] < ti[q]);
                            if (takeA) { rv[o] = va; ri[o] = ai[p]; p++; }
                            else       { rv[o] = vt; ri[o] = ti[q]; q++; }
                        }
#pragma unroll
                        for (int o = 0; o < CAND; o++) { av[o] = rv[o]; ai[o] = ri[o]; }
                    }
                    __syncwarp();
                }
            }
        }
        __syncthreads();   // protect s_sc / sB before next tile
    }

    // exact fp32 rerank of 8 candidates -> true top-5 -> adjacency scatter
    const float* xb = x + (size_t)b * NN * FF;
    for (int rr = 0; rr < 16; rr++) {
        int row = wid * 16 + rr;
        int node = it * 128 + row;
        if (node < NN) {
            int cidx = lane >> 2, dpart = lane & 3;
            int j = s_bi[row * CAND + cidx];
            const float* xi = xb + (size_t)node * FF + dpart * 32;
            const float* xj = xb + (size_t)j * FF + dpart * 32;
            float dot = 0.f;
#pragma unroll
            for (int d = 0; d < 8; d++) {
                float4 va = *(const float4*)(xi + d * 4);
                float4 vb = *(const float4*)(xj + d * 4);
                dot += va.x * vb.x + va.y * vb.y + va.z * vb.z + va.w * vb.w;
            }
            dot += __shfl_xor_sync(0xffffffffu, dot, 1);
            dot += __shfl_xor_sync(0xffffffffu, dot, 2);
            if (dpart == 0) s_tv[wid * CAND + cidx] = s_sq[j] - 2.f * dot;
            __syncwarp();
            if (lane == 0) {
                size_t gi = (size_t)(b * NN + node);
                unsigned used = 0;
#pragma unroll
                for (int o = 0; o < KNN; o++) {
                    float bv = INF; int bj = 0x7fffffff, bc = 0;
#pragma unroll
                    for (int cc = 0; cc < CAND; cc++) {
                        if (!((used >> cc) & 1)) {
                            float v = s_tv[wid * CAND + cc];
                            int vj = s_bi[row * CAND + cc];
                            if (v < bv || (v == bv && vj < bj)) { bv = v; bj = vj; bc = cc; }
                        }
                    }
                    used |= 1u << bc;
                    atomicOr(&g_Abits[gi * 16 + (bj >> 5)], 1u << (bj & 31));
                    atomicOr(&g_Abits[((size_t)(b * NN + bj)) * 16 + (node >> 5)], 1u << (node & 31));
                }
            }
            __syncwarp();
        }
    }
}

// ---------------- mean aggregation (unchanged) ----------------
__global__ void agg_kernel(const float* __restrict__ src, float* __restrict__ dst) {
    __shared__ short s_list[4][NN];
    int w = threadIdx.x >> 5, lane = threadIdx.x & 31;
    int node = blockIdx.x * 4 + w;
    int b = node / NN;
    const unsigned int* Arow = g_Abits + (size_t)node * 16;
    unsigned int m = (lane < 13) ? Arow[lane] : 0u;
    int c = __popc(m);
    int s = c;
#pragma unroll
    for (int o = 1; o < 32; o <<= 1) {
        int v = __shfl_up_sync(0xffffffffu, s, o);
        if (lane >= o) s += v;
    }
    int base = s - c;
    int total = __shfl_sync(0xffffffffu, s, 31);
    unsigned int mm = m; int kpos = 0;
    while (mm) {
        int bit = __ffs(mm) - 1;
        s_list[w][base + kpos] = (short)(lane * 32 + bit);
        kpos++; mm &= mm - 1;
    }
    __syncwarp();
    const float* sb = src + (size_t)b * NN * FF;
    float4 acc = make_float4(0.f, 0.f, 0.f, 0.f);
    for (int e = 0; e < total; e++) {
        float4 v = *(const float4*)(sb + (size_t)s_list[w][e] * FF + lane * 4);
        acc.x += v.x; acc.y += v.y; acc.z += v.z; acc.w += v.w;
    }
    float d = (float)total;
    float4 o = make_float4(acc.x / d, acc.y / d, acc.z / d, acc.w / d);
    *(float4*)(dst + (size_t)node * FF + lane * 4) = o;
}

// ---------------- warp-MMA split-bf16 dual-GEMM (unchanged R8) ----------------
#define MMA_SMEM (4 * 32768)

template <bool RELU>
__global__ void __launch_bounds__(256) mma_gemm(
        const float* __restrict__ Xa, const float* __restrict__ Wa,
        const float* __restrict__ Xb, const float* __restrict__ Wb,
        const float* __restrict__ bias, float* __restrict__ out) {
    extern __shared__ char dsm[];
    char* sAh = dsm;
    char* sAl = dsm + 32768;
    char* sBh = dsm + 65536;
    char* sBl = dsm + 98304;
    const uint32_t aA = smem_u32(dsm);
    const uint32_t aB = aA + 65536;

    const int r0 = blockIdx.x * 128;
    const int t  = threadIdx.x;
    const int wid = t >> 5, lane = t & 31;
    const int wm = wid & 3, wn = wid >> 2;

    const int mat = lane >> 3, mrow = lane & 7;
    const int arow = wm * 32 + ((mat & 1) << 3) + mrow;
    const int aku  = mat >> 1;
    const int ar7  = arow & 7;
    const int brow = wn * 64 + ((mat >> 1) << 3) + mrow;
    const int bku  = mat & 1;
    const int br7  = brow & 7;

    float c[2][8][4] = {};

    for (int src = 0; src < 2; src++) {
        const float* X = src ? Xb : Xa;
        const float* W = src ? Wb : Wa;
        if (src) __syncthreads();
        for (int idx = t; idx < 4096; idx += 256) {
            int row = idx >> 5, c4 = (idx & 31) << 2;
            float4 v = *(const float4*)(X + (size_t)(r0 + row) * FF + c4);
            __nv_bfloat16 h0 = __float2bfloat16(v.x), h1 = __float2bfloat16(v.y);
            __nv_bfloat16 h2 = __float2bfloat16(v.z), h3 = __float2bfloat16(v.w);
            uint32_t off = toff(row, c4);
            *(uint2*)(sAh + off) = make_uint2(pk_bf(h0, h1), pk_bf(h2, h3));
            *(uint2*)(sAl + off) = make_uint2(
                pk_bf(__float2bfloat16(v.x - __bfloat162float(h0)), __float2bfloat16(v.y - __bfloat162float(h1))),
                pk_bf(__float2bfloat16(v.z - __bfloat162float(h2)), __float2bfloat16(v.w - __bfloat162float(h3))));
        }
        for (int idx = t; idx < 4096; idx += 256) {
            int row = idx >> 5, c4 = (idx & 31) << 2;
            float4 v = *(const float4*)(W + (size_t)row * FF + c4);
            __nv_bfloat16 h0 = __float2bfloat16(v.x), h1 = __float2bfloat16(v.y);
            __nv_bfloat16 h2 = __float2bfloat16(v.z), h3 = __float2bfloat16(v.w);
            uint32_t off = toff(row, c4);
            *(uint2*)(sBh + off) = make_uint2(pk_bf(h0, h1), pk_bf(h2, h3));
            *(uint2*)(sBl + off) = make_uint2(
                pk_bf(__float2bfloat16(v.x - __bfloat162float(h0)), __float2bfloat16(v.y - __bfloat162float(h1))),
                pk_bf(__float2bfloat16(v.z - __bfloat162float(h2)), __float2bfloat16(v.w - __bfloat162float(h3))));
        }
        __syncthreads();

        for (int pass = 0; pass < 3; pass++) {
            const uint32_t baseA = aA + (pass == 2 ? 32768u : 0u);
            const uint32_t baseB = aB + (pass == 1 ? 32768u : 0u);
            const uint32_t rowA0 = baseA + (uint32_t)arow * 256;
            const uint32_t rowA1 = baseA + (uint32_t)(arow + 16) * 256;
            const uint32_t rowB0 = baseB + (uint32_t)brow * 256;
#pragma unroll
            for (int ks = 0; ks < 8; ks++) {
                uint32_t a[2][4], bfr[4][4];
                uint32_t ua = (uint32_t)(((ks * 2 + aku) ^ ar7) << 4);
                ldm_x4(a[0], rowA0 + ua);
                ldm_x4(a[1], rowA1 + ua);
                uint32_t ub = (uint32_t)(((ks * 2 + bku) ^ br7) << 4);
#pragma unroll
                for (int nc = 0; nc < 4; nc++)
                    ldm_x4(bfr[nc], rowB0 + (uint32_t)nc * 16 * 256 + ub);
#pragma unroll
                for (int mt = 0; mt < 2; mt++)
#pragma unroll
                    for (int nf = 0; nf < 8; nf++)
                        mma16816(c[mt][nf], a[mt], &bfr[nf >> 1][(nf & 1) * 2]);
            }
        }
    }

    const int l4 = lane >> 2, l2 = (lane & 3) * 2;
#pragma unroll
    for (int mt = 0; mt < 2; mt++) {
        int row = r0 + wm * 32 + mt * 16 + l4;
#pragma unroll
        for (int nf = 0; nf < 8; nf++) {
            int col = wn * 64 + nf * 8 + l2;
            float b0 = bias[col], b1 = bias[col + 1];
            float v0 = c[mt][nf][0] + b0, v1 = c[mt][nf][1] + b1;
            float v2 = c[mt][nf][2] + b0, v3 = c[mt][nf][3] + b1;
            if (RELU) {
                v0 = fmaxf(v0, 0.f); v1 = fmaxf(v1, 0.f);
                v2 = fmaxf(v2, 0.f); v3 = fmaxf(v3, 0.f);
            }
            *(float2*)(out + (size_t)row * FF + col) = make_float2(v0, v1);
            *(float2*)(out + (size_t)(row + 8) * FF + col) = make_float2(v2, v3);
        }
    }
}

// ---------------- launch ----------------
extern "C" void kernel_launch(void* const* d_in, const int* in_sizes, int n_in,
                              void* d_out, int out_size) {
    const float* x   = (const float*)d_in[0];
    const float* W1l = (const float*)d_in[1];
    const float* b1l = (const float*)d_in[2];
    const float* W1r = (const float*)d_in[3];
    const float* W2l = (const float*)d_in[4];
    const float* b2l = (const float*)d_in[5];
    const float* W2r = (const float*)d_in[6];
    float* out = (float*)d_out;

    void* aptr = nullptr;
    cudaGetSymbolAddress(&aptr, g_Abits);
    float* mp = nullptr; cudaGetSymbolAddress((void**)&mp, g_m);
    float* hp = nullptr; cudaGetSymbolAddress((void**)&hp, g_h);

    cudaFuncSetAttribute(knn2_kernel, cudaFuncAttributeMaxDynamicSharedMemorySize, KNN2_SMEM);
    cudaFuncSetAttribute(mma_gemm<true>,  cudaFuncAttributeMaxDynamicSharedMemorySize, MMA_SMEM);
    cudaFuncSetAttribute(mma_gemm<false>, cudaFuncAttributeMaxDynamicSharedMemorySize, MMA_SMEM);

    cudaMemsetAsync(aptr, 0, (size_t)BN * 16 * sizeof(unsigned int), 0);
    sq_kernel<<<BN / 4, 128>>>(x);
    dim3 xg(4, BB);
    xsplit_kernel<<<xg, 256>>>(x);
    knn2_kernel<<<xg, 256, KNN2_SMEM>>>(x);
    agg_kernel<<<BN / 4, 128>>>(x, mp);
    mma_gemm<true><<<BN / 128, 256, MMA_SMEM>>>(mp, W1l, x, W1r, b1l, hp);
    agg_kernel<<<BN / 4, 128>>>(hp, mp);
    mma_gemm<false><<<BN / 128, 256, MMA_SMEM>>>(mp, W2l, hp, W2r, b2l, out);
}

// round 11
// speedup vs baseline: 2.0008x; 2.0008x over previous
#include <cuda_runtime.h>
#include <cuda_bf16.h>
#include <cstdint>
#include <cstddef>

#define BB 128
#define NN 400
#define FF 128
#define KNN 5
#define BN (BB * NN)   // 51200

// ---------------- device scratch ----------------
__device__ float g_sq[BN];
__device__ unsigned int g_Abits[(size_t)BN * 16];  // 400-bit adjacency rows, 3.3MB
__device__ float g_m[(size_t)BN * FF];
__device__ float g_h[(size_t)BN * FF];

// ---------------- warp-MMA helpers (base-target PTX: ldmatrix + mma.sync) ----------------
__device__ __forceinline__ uint32_t smem_u32(const void* p) {
    uint32_t a;
    asm("{ .reg .u64 t; cvta.to.shared.u64 t, %1; cvt.u32.u64 %0, t; }" : "=r"(a) : "l"(p));
    return a;
}
__device__ __forceinline__ void ldm_x4(uint32_t* r, uint32_t addr) {
    asm volatile("ldmatrix.sync.aligned.m8n8.x4.shared.b16 {%0,%1,%2,%3}, [%4];"
        : "=r"(r[0]), "=r"(r[1]), "=r"(r[2]), "=r"(r[3]) : "r"(addr));
}
__device__ __forceinline__ void mma16816(float* c, const uint32_t* a, const uint32_t* b) {
    asm volatile("mma.sync.aligned.m16n8k16.row.col.f32.bf16.bf16.f32 "
        "{%0,%1,%2,%3}, {%4,%5,%6,%7}, {%8,%9}, {%0,%1,%2,%3};"
        : "+f"(c[0]), "+f"(c[1]), "+f"(c[2]), "+f"(c[3])
        : "r"(a[0]), "r"(a[1]), "r"(a[2]), "r"(a[3]), "r"(b[0]), "r"(b[1]));
}
// bf16 tile row stride 256B, 16B-unit swizzle u' = u ^ (row&7)
__device__ __forceinline__ uint32_t toff(int row, int k) {   // k in bf16 elems
    return (uint32_t)(row * 256 + ((((k >> 3) ^ (row & 7)) << 4) | ((k & 7) << 1)));
}
__device__ __forceinline__ uint32_t pk_bf(__nv_bfloat16 a, __nv_bfloat16 b) {
    return (uint32_t)__bfloat16_as_ushort(a) | ((uint32_t)__bfloat16_as_ushort(b) << 16);
}

// ---------------- no-op (launch-slot padding so ncu lands on knn) ----------------
__global__ void nop_kernel() {}

// ---------------- squared norms ----------------
__global__ void sq_kernel(const float* __restrict__ x) {
    int row = blockIdx.x * 4 + (threadIdx.x >> 5);
    int lane = threadIdx.x & 31;
    float4 v = *(const float4*)(x + (size_t)row * FF + lane * 4);
    float s = v.x * v.x + v.y * v.y + v.z * v.z + v.w * v.w;
#pragma unroll
    for (int o = 16; o; o >>= 1) s += __shfl_xor_sync(0xffffffffu, s, o);
    if (lane == 0) g_sq[row] = s;
}

// ---------------- fused distance + top-5 + adjacency scatter (R6/R8 scalar) ----------------
#define KNN_SMEM ((128 * 64 + 128 * 128 + 416 + 64 * 5 * 2 + 8 * 5 * 2) * 4)

__global__ void __launch_bounds__(256, 2) knn_kernel(const float* __restrict__ x) {
    extern __shared__ float sm[];
    float* s_xiT = sm;
    float* s_xjT = s_xiT + 128 * 64;
    float* s_sq  = s_xjT + 128 * 128;
    float* s_bv  = s_sq + 416;
    int*   s_bi  = (int*)(s_bv + 64 * 5);
    float* s_tv  = (float*)(s_bi + 64 * 5);
    int*   s_ti  = (int*)(s_tv + 8 * 5);

    const int b  = blockIdx.y;
    const int i0 = blockIdx.x * 64;
    const int t  = threadIdx.x;
    const int tx = t & 31, ty = t >> 5;
    const int lane = t & 31;
    const float INF = __int_as_float(0x7f800000);
    const float* xb = x + (size_t)b * NN * FF;

    for (int j = t; j < NN; j += 256) s_sq[j] = g_sq[b * NN + j];
    for (int q = t; q < 64 * KNN; q += 256) { s_bv[q] = INF; s_bi[q] = 0x7fffffff; }

    for (int idx = t; idx < 512; idx += 256) {
        int ob = idx >> 5, kc = idx & 31;
        float vv[4][4];
#pragma unroll
        for (int r = 0; r < 4; r++) {
            int ir = i0 + ob * 4 + r;
            float4 v = (ir < NN) ? *(const float4*)(xb + (size_t)ir * FF + kc * 4)
                                 : make_float4(0.f, 0.f, 0.f, 0.f);
            vv[r][0] = v.x; vv[r][1] = v.y; vv[r][2] = v.z; vv[r][3] = v.w;
        }
#pragma unroll
        for (int c = 0; c < 4; c++)
            *(float4*)&s_xiT[(kc * 4 + c) * 64 + (((ob ^ kc) & 15) << 2)] =
                make_float4(vv[0][c], vv[1][c], vv[2][c], vv[3][c]);
    }

    for (int j0 = 0; j0 < NN; j0 += 128) {
        __syncthreads();
        for (int idx = t; idx < 1024; idx += 256) {
            int ob = idx >> 5, kc = idx & 31;
            float vv[4][4];
#pragma unroll
            for (int r = 0; r < 4; r++) {
                int jr = j0 + ob * 4 + r;
                float4 v = (jr < NN) ? *(const float4*)(xb + (size_t)jr * FF + kc * 4)
                                     : make_float4(0.f, 0.f, 0.f, 0.f);
                vv[r][0] = v.x; vv[r][1] = v.y; vv[r][2] = v.z; vv[r][3] = v.w;
            }
#pragma unroll
            for (int c = 0; c < 4; c++)
                *(float4*)&s_xjT[(kc * 4 + c) * 128 + (((ob ^ kc) & 31) << 2)] =
                    make_float4(vv[0][c], vv[1][c], vv[2][c], vv[3][c]);
        }
        __syncthreads();

        float acc[8][4] = {};
#pragma unroll 4
        for (int k = 0; k < 128; k++) {
            int sw = k >> 2;
            float4 a0 = *(const float4*)&s_xiT[k * 64  + ((((2 * ty)     ^ sw) & 15) << 2)];
            float4 a1 = *(const float4*)&s_xiT[k * 64  + ((((2 * ty + 1) ^ sw) & 15) << 2)];
            float4 bj = *(const float4*)&s_xjT[k * 128 + (((tx ^ sw) & 31) << 2)];
            acc[0][0] += a0.x * bj.x; acc[0][1] += a0.x * bj.y; acc[0][2] += a0.x * bj.z; acc[0][3] += a0.x * bj.w;
            acc[1][0] += a0.y * bj.x; acc[1][1] += a0.y * bj.y; acc[1][2] += a0.y * bj.z; acc[1][3] += a0.y * bj.w;
            acc[2][0] += a0.z * bj.x; acc[2][1] += a0.z * bj.y; acc[2][2] += a0.z * bj.z; acc[2][3] += a0.z * bj.w;
            acc[3][0] += a0.w * bj.x; acc[3][1] += a0.w * bj.y; acc[3][2] += a0.w * bj.z; acc[3][3] += a0.w * bj.w;
            acc[4][0] += a1.x * bj.x; acc[4][1] += a1.x * bj.y; acc[4][2] += a1.x * bj.z; acc[4][3] += a1.x * bj.w;
            acc[5][0] += a1.y * bj.x; acc[5][1] += a1.y * bj.y; acc[5][2] += a1.y * bj.z; acc[5][3] += a1.y * bj.w;
            acc[6][0] += a1.z * bj.x; acc[6][1] += a1.z * bj.y; acc[6][2] += a1.z * bj.z; acc[6][3] += a1.z * bj.w;
            acc[7][0] += a1.w * bj.x; acc[7][1] += a1.w * bj.y; acc[7][2] += a1.w * bj.z; acc[7][3] += a1.w * bj.w;
        }

        float scv[8][4];
#pragma unroll
        for (int rr = 0; rr < 8; rr++)
#pragma unroll
            for (int c = 0; c < 4; c++) {
                int jg = j0 + tx * 4 + c;
                scv[rr][c] = (jg < NN) ? s_sq[jg] - 2.f * acc[rr][c] : INF;
            }

#pragma unroll
        for (int rr = 0; rr < 8; rr++) {
            int li = ty * 8 + rr;
            int irow = i0 + li;
            if (irow < NN) {
                float kv = s_bv[li * KNN + 4];
                int   ki = s_bi[li * KNN + 4];
                bool cand = false;
#pragma unroll
                for (int c = 0; c < 4; c++) {
                    float v = scv[rr][c];
                    int jg = j0 + tx * 4 + c;
                    cand |= (v < kv) || (v == kv && jg < ki);
                }
                if (__ballot_sync(0xffffffffu, cand)) {
                    if (lane < KNN) { s_tv[ty * KNN + lane] = INF; s_ti[ty * KNN + lane] = 0x7fffffff; }
                    __syncwarp();
                    for (int q = 0; q < KNN; q++) {
                        float bv = scv[rr][0]; int bc = 0;
                        if (scv[rr][1] < bv) { bv = scv[rr][1]; bc = 1; }
                        if (scv[rr][2] < bv) { bv = scv[rr][2]; bc = 2; }
                        if (scv[rr][3] < bv) { bv = scv[rr][3]; bc = 3; }
                        int bj = j0 + tx * 4 + bc;
#pragma unroll
                        for (int o = 16; o; o >>= 1) {
                            float ov = __shfl_xor_sync(0xffffffffu, bv, o);
                            int   oj = __shfl_xor_sync(0xffffffffu, bj, o);
                            if (ov < bv || (ov == bv && oj < bj)) { bv = ov; bj = oj; }
                        }
                        bool beats = (bv < kv) || (bv == kv && bj < ki);
                        if (!beats) break;
                        if (lane == 0) { s_tv[ty * KNN + q] = bv; s_ti[ty * KNN + q] = bj; }
                        int lc = bj - j0 - tx * 4;
                        if (lc == 0) scv[rr][0] = INF;
                        if (lc == 1) scv[rr][1] = INF;
                        if (lc == 2) scv[rr][2] = INF;
                        if (lc == 3) scv[rr][3] = INF;
                    }
                    __syncwarp();
                    if (lane == 0) {
                        float rv[KNN]; int ri[KNN];
                        float* av = &s_bv[li * KNN]; int* ai = &s_bi[li * KNN];
                        float* tv = &s_tv[ty * KNN]; int* ti = &s_ti[ty * KNN];
                        int p = 0, q = 0;
#pragma unroll
                        for (int o = 0; o < KNN; o++) {
                            float va = av[p], vt = tv[q];
                            bool takeA = (va < vt) || (va == vt && ai[p] < ti[q]);
                            if (takeA) { rv[o] = va; ri[o] = ai[p]; p++; }
                            else       { rv[o] = vt; ri[o] = ti[q]; q++; }
                        }
#pragma unroll
                        for (int o = 0; o < KNN; o++) { av[o] = rv[o]; ai[o] = ri[o]; }
                    }
                    __syncwarp();
                }
            }
        }
    }
    __syncthreads();

    if (t < 64) {
        int il = i0 + t;
        if (il < NN) {
            size_t gi = (size_t)(b * NN + il);
#pragma unroll
            for (int q = 0; q < KNN; q++) {
                int j = s_bi[t * KNN + q];
                atomicOr(&g_Abits[gi * 16 + (j >> 5)], 1u << (j & 31));
                atomicOr(&g_Abits[((size_t)(b * NN + j)) * 16 + (il >> 5)], 1u << (il & 31));
            }
        }
    }
}

// ---------------- mean aggregation (unchanged) ----------------
__global__ void agg_kernel(const float* __restrict__ src, float* __restrict__ dst) {
    __shared__ short s_list[4][NN];
    int w = threadIdx.x >> 5, lane = threadIdx.x & 31;
    int node = blockIdx.x * 4 + w;
    int b = node / NN;
    const unsigned int* Arow = g_Abits + (size_t)node * 16;
    unsigned int m = (lane < 13) ? Arow[lane] : 0u;
    int c = __popc(m);
    int s = c;
#pragma unroll
    for (int o = 1; o < 32; o <<= 1) {
        int v = __shfl_up_sync(0xffffffffu, s, o);
        if (lane >= o) s += v;
    }
    int base = s - c;
    int total = __shfl_sync(0xffffffffu, s, 31);
    unsigned int mm = m; int kpos = 0;
    while (mm) {
        int bit = __ffs(mm) - 1;
        s_list[w][base + kpos] = (short)(lane * 32 + bit);
        kpos++; mm &= mm - 1;
    }
    __syncwarp();
    const float* sb = src + (size_t)b * NN * FF;
    float4 acc = make_float4(0.f, 0.f, 0.f, 0.f);
    for (int e = 0; e < total; e++) {
        float4 v = *(const float4*)(sb + (size_t)s_list[w][e] * FF + lane * 4);
        acc.x += v.x; acc.y += v.y; acc.z += v.z; acc.w += v.w;
    }
    float d = (float)total;
    float4 o = make_float4(acc.x / d, acc.y / d, acc.z / d, acc.w / d);
    *(float4*)(dst + (size_t)node * FF + lane * 4) = o;
}

// ---------------- warp-MMA split-bf16 dual-GEMM, M-tile 64 (2 CTAs/SM) ----------------
// out[r0..r0+64][128] = act( Xa@Wa^T + Xb@Wb^T + bias ); 3-pass: Ah*Bh + Ah*Bl + Al*Bh
// smem: Ah 16K | Al 16K | Bh 32K | Bl 32K = 96KB
#define MMA_SMEM (2 * 16384 + 2 * 32768)

template <bool RELU>
__global__ void __launch_bounds__(256) mma_gemm(
        const float* __restrict__ Xa, const float* __restrict__ Wa,
        const float* __restrict__ Xb, const float* __restrict__ Wb,
        const float* __restrict__ bias, float* __restrict__ out) {
    extern __shared__ char dsm[];
    char* sAh = dsm;                 // 64 x 128 bf16
    char* sAl = dsm + 16384;
    char* sBh = dsm + 32768;         // 128 x 128 bf16
    char* sBl = dsm + 65536;
    const uint32_t aA = smem_u32(dsm);
    const uint32_t aB = aA + 32768;

    const int r0 = blockIdx.x * 64;
    const int t  = threadIdx.x;
    const int wid = t >> 5, lane = t & 31;
    const int wm = wid & 1, wn = wid >> 1;      // warp tile: rows wm*32..+31, cols wn*32..+31

    const int mat = lane >> 3, mrow = lane & 7;
    const int arow = wm * 32 + ((mat & 1) << 3) + mrow;
    const int aku  = mat >> 1;
    const int ar7  = arow & 7;
    const int brow = wn * 32 + ((mat >> 1) << 3) + mrow;
    const int bku  = mat & 1;
    const int br7  = brow & 7;

    float c[2][4][4] = {};

    for (int src = 0; src < 2; src++) {
        const float* X = src ? Xb : Xa;
        const float* W = src ? Wb : Wa;
        if (src) __syncthreads();
        // A: 64 rows x 128 k
        for (int idx = t; idx < 2048; idx += 256) {
            int row = idx >> 5, c4 = (idx & 31) << 2;
            float4 v = *(const float4*)(X + (size_t)(r0 + row) * FF + c4);
            __nv_bfloat16 h0 = __float2bfloat16(v.x), h1 = __float2bfloat16(v.y);
            __nv_bfloat16 h2 = __float2bfloat16(v.z), h3 = __float2bfloat16(v.w);
            uint32_t off = toff(row, c4);
            *(uint2*)(sAh + off) = make_uint2(pk_bf(h0, h1), pk_bf(h2, h3));
            *(uint2*)(sAl + off) = make_uint2(
                pk_bf(__float2bfloat16(v.x - __bfloat162float(h0)), __float2bfloat16(v.y - __bfloat162float(h1))),
                pk_bf(__float2bfloat16(v.z - __bfloat162float(h2)), __float2bfloat16(v.w - __bfloat162float(h3))));
        }
        // B: 128 out-cols x 128 k
        for (int idx = t; idx < 4096; idx += 256) {
            int row = idx >> 5, c4 = (idx & 31) << 2;
            float4 v = *(const float4*)(W + (size_t)row * FF + c4);
            __nv_bfloat16 h0 = __float2bfloat16(v.x), h1 = __float2bfloat16(v.y);
            __nv_bfloat16 h2 = __float2bfloat16(v.z), h3 = __float2bfloat16(v.w);
            uint32_t off = toff(row, c4);
            *(uint2*)(sBh + off) = make_uint2(pk_bf(h0, h1), pk_bf(h2, h3));
            *(uint2*)(sBl + off) = make_uint2(
                pk_bf(__float2bfloat16(v.x - __bfloat162float(h0)), __float2bfloat16(v.y - __bfloat162float(h1))),
                pk_bf(__float2bfloat16(v.z - __bfloat162float(h2)), __float2bfloat16(v.w - __bfloat162float(h3))));
        }
        __syncthreads();

        for (int pass = 0; pass < 3; pass++) {
            const uint32_t baseA = aA + (pass == 2 ? 16384u : 0u);
            const uint32_t baseB = aB + (pass == 1 ? 32768u : 0u);
            const uint32_t rowA0 = baseA + (uint32_t)arow * 256;
            const uint32_t rowA1 = rowA0 + 16 * 256;
            const uint32_t rowB0 = baseB + (uint32_t)brow * 256;
#pragma unroll
            for (int ks = 0; ks < 8; ks++) {
                uint32_t a0[4], a1[4], b0[4], b1[4];
                uint32_t ua = (uint32_t)(((ks * 2 + aku) ^ ar7) << 4);
                ldm_x4(a0, rowA0 + ua);
                ldm_x4(a1, rowA1 + ua);
                uint32_t ub = (uint32_t)(((ks * 2 + bku) ^ br7) << 4);
                ldm_x4(b0, rowB0 + ub);
                ldm_x4(b1, rowB0 + 16 * 256 + ub);
                mma16816(c[0][0], a0, &b0[0]); mma16816(c[0][1], a0, &b0[2]);
                mma16816(c[0][2], a0, &b1[0]); mma16816(c[0][3], a0, &b1[2]);
                mma16816(c[1][0], a1, &b0[0]); mma16816(c[1][1], a1, &b0[2]);
                mma16816(c[1][2], a1, &b1[0]); mma16816(c[1][3], a1, &b1[2]);
            }
        }
    }

    const int l4 = lane >> 2, l2 = (lane & 3) * 2;
#pragma unroll
    for (int mt = 0; mt < 2; mt++) {
        int row = r0 + wm * 32 + mt * 16 + l4;
#pragma unroll
        for (int nf = 0; nf < 4; nf++) {
            int col = wn * 32 + nf * 8 + l2;
            float b0 = bias[col], b1 = bias[col + 1];
            float v0 = c[mt][nf][0] + b0, v1 = c[mt][nf][1] + b1;
            float v2 = c[mt][nf][2] + b0, v3 = c[mt][nf][3] + b1;
            if (RELU) {
                v0 = fmaxf(v0, 0.f); v1 = fmaxf(v1, 0.f);
                v2 = fmaxf(v2, 0.f); v3 = fmaxf(v3, 0.f);
            }
            *(float2*)(out + (size_t)row * FF + col) = make_float2(v0, v1);
            *(float2*)(out + (size_t)(row + 8) * FF + col) = make_float2(v2, v3);
        }
    }
}

// ---------------- launch ----------------
extern "C" void kernel_launch(void* const* d_in, const int* in_sizes, int n_in,
                              void* d_out, int out_size) {
    const float* x   = (const float*)d_in[0];
    const float* W1l = (const float*)d_in[1];
    const float* b1l = (const float*)d_in[2];
    const float* W1r = (const float*)d_in[3];
    const float* W2l = (const float*)d_in[4];
    const float* b2l = (const float*)d_in[5];
    const float* W2r = (const float*)d_in[6];
    float* out = (float*)d_out;

    void* aptr = nullptr;
    cudaGetSymbolAddress(&aptr, g_Abits);
    float* mp = nullptr; cudaGetSymbolAddress((void**)&mp, g_m);
    float* hp = nullptr; cudaGetSymbolAddress((void**)&hp, g_h);

    cudaFuncSetAttribute(knn_kernel, cudaFuncAttributeMaxDynamicSharedMemorySize, KNN_SMEM);
    cudaFuncSetAttribute(mma_gemm<true>,  cudaFuncAttributeMaxDynamicSharedMemorySize, MMA_SMEM);
    cudaFuncSetAttribute(mma_gemm<false>, cudaFuncAttributeMaxDynamicSharedMemorySize, MMA_SMEM);

    cudaMemsetAsync(aptr, 0, (size_t)BN * 16 * sizeof(unsigned int), 0);
    sq_kernel<<<BN / 4, 128>>>(x);          // launch 0
    nop_kernel<<<1, 32>>>();                // launch 1
    nop_kernel<<<1, 32>>>();                // launch 2
    dim3 kg(7, BB);
    knn_kernel<<<kg, 256, KNN_SMEM>>>(x);   // launch 3  <- ncu profiles this one
    agg_kernel<<<BN / 4, 128>>>(x, mp);
    mma_gemm<true><<<BN / 64, 256, MMA_SMEM>>>(mp, W1l, x, W1r, b1l, hp);
    agg_kernel<<<BN / 4, 128>>>(hp, mp);
    mma_gemm<false><<<BN / 64, 256, MMA_SMEM>>>(mp, W2l, hp, W2r, b2l, out);
}